// round 1
// baseline (speedup 1.0000x reference)
#include <cuda_runtime.h>
#include <math.h>

#define BB 4
#define CC 64
#define FF 256
#define TT 400
#define DC 16
#define SP (FF*TT)   /* 102400 spatial per (b,c) */

// ---------------- scratch (static device arrays; no allocation) ----------------
static __device__ float g_qkvf_t[(size_t)BB*48*FF*TT];  // [b][oc48][f][t]
static __device__ float g_qkvf_f[(size_t)BB*TT*48*FF];  // [b][t][oc48][f]
static __device__ float g_tqk  [(size_t)BB*FF*32*TT];   // [b][f][oc32][t]
static __device__ float g_fout_t[(size_t)BB*TT*DC*FF];  // [b][t][c][f]
static __device__ float g_fout_f[(size_t)BB*FF*DC*TT];  // [b][f][c][t]

// ---------------- kernel 1: fused conv1x1 (fqkv|tqk) + BN + PReLU ----------------
__global__ __launch_bounds__(128)
void asa_conv_qkv_kernel(const float* __restrict__ inp,
    const float* __restrict__ w_fqkv, const float* __restrict__ w_tqk,
    const float* __restrict__ g1, const float* __restrict__ b1,
    const float* __restrict__ m1, const float* __restrict__ v1, const float* __restrict__ a1,
    const float* __restrict__ g2, const float* __restrict__ b2,
    const float* __restrict__ m2, const float* __restrict__ v2, const float* __restrict__ a2)
{
    __shared__ float wsm[80*64];
    __shared__ float scs[80], shs[80], als[80];
    int f = blockIdx.x, b = blockIdx.y;
    int tid = threadIdx.x;
    for (int i = tid; i < 3072; i += 128) wsm[i]        = w_fqkv[i];
    for (int i = tid; i < 2048; i += 128) wsm[3072 + i] = w_tqk[i];
    if (tid < 80) {
        float g, bi, mi, vi, ai;
        if (tid < 48) { g = g1[tid]; bi = b1[tid]; mi = m1[tid]; vi = v1[tid]; ai = a1[tid]; }
        else { int j = tid - 48; g = g2[j]; bi = b2[j]; mi = m2[j]; vi = v2[j]; ai = a2[j]; }
        float s = g * rsqrtf(vi + 1e-5f);
        scs[tid] = s; shs[tid] = bi - mi * s; als[tid] = ai;
    }
    __syncthreads();
    if (tid >= 100) return;
    int t4 = tid * 4;
    size_t base = (((size_t)b * CC) * FF + f) * TT + t4;

    for (int oc0 = 0; oc0 < 80; oc0 += 16) {
        float ax[16], ay[16], az[16], aw[16];
        #pragma unroll
        for (int j = 0; j < 16; j++) { ax[j] = ay[j] = az[j] = aw[j] = 0.f; }
        #pragma unroll 4
        for (int c = 0; c < 64; c++) {
            float4 iv = *(const float4*)(inp + base + (size_t)c * SP);
            #pragma unroll
            for (int j = 0; j < 16; j++) {
                float w = wsm[(oc0 + j) * 64 + c];
                ax[j] = fmaf(w, iv.x, ax[j]);
                ay[j] = fmaf(w, iv.y, ay[j]);
                az[j] = fmaf(w, iv.z, az[j]);
                aw[j] = fmaf(w, iv.w, aw[j]);
            }
        }
        #pragma unroll
        for (int j = 0; j < 16; j++) {
            int oc = oc0 + j;
            float s = scs[oc], sh = shs[oc], al = als[oc];
            float4 r;
            r.x = fmaf(ax[j], s, sh); r.y = fmaf(ay[j], s, sh);
            r.z = fmaf(az[j], s, sh); r.w = fmaf(aw[j], s, sh);
            r.x = r.x > 0.f ? r.x : al * r.x;
            r.y = r.y > 0.f ? r.y : al * r.y;
            r.z = r.z > 0.f ? r.z : al * r.z;
            r.w = r.w > 0.f ? r.w : al * r.w;
            if (oc < 48) {
                *(float4*)&g_qkvf_t[(((size_t)b * 48 + oc) * FF + f) * TT + t4] = r;
            } else {
                *(float4*)&g_tqk[(((size_t)b * FF + f) * 32 + (oc - 48)) * TT + t4] = r;
            }
        }
    }
}

// ---------------- transpose 1: [b][oc][f][t] -> [b][t][oc][f] ----------------
__global__ __launch_bounds__(256)
void asa_transpose_qkv_kernel()
{
    __shared__ float tile[32][33];
    int z = blockIdx.z;                 // b*48 + oc
    int t0 = blockIdx.x * 32, f0 = blockIdx.y * 32;
    int tx = threadIdx.x, ty = threadIdx.y;
    size_t ibase = (size_t)z * FF * TT;
    #pragma unroll
    for (int k = 0; k < 32; k += 8) {
        int t = t0 + tx, f = f0 + ty + k;
        if (t < TT) tile[ty + k][tx] = g_qkvf_t[ibase + (size_t)f * TT + t];
    }
    __syncthreads();
    int b = z / 48, oc = z % 48;
    #pragma unroll
    for (int k = 0; k < 32; k += 8) {
        int t = t0 + ty + k, f = f0 + tx;
        if (t < TT) g_qkvf_f[((size_t)(b * TT + t) * 48 + oc) * FF + f] = tile[tx][ty + k];
    }
}

// ---------------- kernel 2: frequency attention, one (b,t) per block ----------------
__global__ __launch_bounds__(256)
void asa_freq_attn_kernel()
{
    __shared__ float ks[16 * 256];
    __shared__ float vs[16 * 256];
    int t = blockIdx.x, b = blockIdx.y;
    int f = threadIdx.x;
    const float* base = g_qkvf_f + (size_t)(b * TT + t) * 48 * FF;
    for (int i = f; i < 4096; i += 256) { ks[i] = base[4096 + i]; vs[i] = base[8192 + i]; }
    __syncthreads();

    float q[16];
    #pragma unroll
    for (int c = 0; c < 16; c++) q[c] = base[c * 256 + f] * 0.25f;  // fold 1/sqrt(d_c)

    float mx = -3e38f, l = 0.f, acc[16];
    #pragma unroll
    for (int c = 0; c < 16; c++) acc[c] = 0.f;

    for (int y0 = 0; y0 < 256; y0 += 32) {
        float s[32];
        #pragma unroll
        for (int i = 0; i < 32; i++) s[i] = 0.f;
        #pragma unroll
        for (int c = 0; c < 16; c++) {
            const float4* kp = (const float4*)(ks + c * 256 + y0);
            float qc = q[c];
            #pragma unroll
            for (int j = 0; j < 8; j++) {
                float4 k4 = kp[j];
                s[4*j+0] = fmaf(qc, k4.x, s[4*j+0]);
                s[4*j+1] = fmaf(qc, k4.y, s[4*j+1]);
                s[4*j+2] = fmaf(qc, k4.z, s[4*j+2]);
                s[4*j+3] = fmaf(qc, k4.w, s[4*j+3]);
            }
        }
        float cm = s[0];
        #pragma unroll
        for (int i = 1; i < 32; i++) cm = fmaxf(cm, s[i]);
        float nm = fmaxf(mx, cm);
        float corr = __expf(mx - nm);
        l *= corr;
        #pragma unroll
        for (int c = 0; c < 16; c++) acc[c] *= corr;
        float ps = 0.f;
        #pragma unroll
        for (int i = 0; i < 32; i++) { s[i] = __expf(s[i] - nm); ps += s[i]; }
        l += ps;
        #pragma unroll
        for (int c = 0; c < 16; c++) {
            const float4* vp = (const float4*)(vs + c * 256 + y0);
            float a = acc[c];
            #pragma unroll
            for (int j = 0; j < 8; j++) {
                float4 v4 = vp[j];
                a = fmaf(s[4*j+0], v4.x, a);
                a = fmaf(s[4*j+1], v4.y, a);
                a = fmaf(s[4*j+2], v4.z, a);
                a = fmaf(s[4*j+3], v4.w, a);
            }
            acc[c] = a;
        }
        mx = nm;
    }
    float inv = 1.f / l;
    size_t ob = (size_t)(b * TT + t) * DC * FF + f;
    #pragma unroll
    for (int c = 0; c < 16; c++) g_fout_t[ob + c * 256] = acc[c] * inv;
}

// ---------------- transpose 2: [b][t][c][f] -> [b][f][c][t] ----------------
__global__ __launch_bounds__(256)
void asa_transpose_fout_kernel()
{
    __shared__ float tile[32][33];
    int z = blockIdx.z;                 // b*16 + c
    int f0 = blockIdx.x * 32, t0 = blockIdx.y * 32;
    int tx = threadIdx.x, ty = threadIdx.y;
    int b = z / 16, c = z % 16;
    #pragma unroll
    for (int k = 0; k < 32; k += 8) {
        int t = t0 + ty + k, f = f0 + tx;
        if (t < TT) tile[ty + k][tx] = g_fout_t[((size_t)(b * TT + t) * DC + c) * FF + f];
    }
    __syncthreads();
    #pragma unroll
    for (int k = 0; k < 32; k += 8) {
        int f = f0 + ty + k, t = t0 + tx;
        if (t < TT) g_fout_f[((size_t)(b * FF + f) * DC + c) * TT + t] = tile[tx][ty + k];
    }
}

// ---- kernel 3: causal time attention + proj conv + BN + PReLU + residual ----
__global__ __launch_bounds__(416)
void asa_time_attn_kernel(const float* __restrict__ inp, const float* __restrict__ w_proj,
    const float* __restrict__ g3, const float* __restrict__ b3, const float* __restrict__ m3,
    const float* __restrict__ v3, const float* __restrict__ a3, float* __restrict__ out)
{
    extern __shared__ float sm[];
    float* kt  = sm;            // 16*400
    float* vf  = sm + 6400;     // 16*400
    float* wp  = sm + 12800;    // 64*16
    float* sc3 = sm + 13824;
    float* sh3 = sm + 13888;
    float* al3 = sm + 13952;    // total 14016 floats = 56064 B

    int f = blockIdx.x, b = blockIdx.y;
    int tid = threadIdx.x;
    size_t tbase = (size_t)(b * FF + f) * 32 * TT;
    size_t fbase = (size_t)(b * FF + f) * DC * TT;
    for (int i = tid; i < 6400; i += 416) kt[i] = g_tqk[tbase + 6400 + i];
    for (int i = tid; i < 6400; i += 416) vf[i] = g_fout_f[fbase + i];
    for (int i = tid; i < 1024; i += 416) wp[i] = w_proj[i];
    if (tid < 64) {
        float s = g3[tid] * rsqrtf(v3[tid] + 1e-5f);
        sc3[tid] = s; sh3[tid] = b3[tid] - m3[tid] * s; al3[tid] = a3[tid];
    }
    __syncthreads();
    if (tid >= TT) return;
    int t = tid;

    float q[16];
    #pragma unroll
    for (int c = 0; c < 16; c++) q[c] = g_tqk[tbase + c * TT + t] * 0.25f;

    float mx = -3e38f, l = 0.f, acc[16];
    #pragma unroll
    for (int c = 0; c < 16; c++) acc[c] = 0.f;

    int nch = (t >> 5) + 1;
    for (int ch = 0; ch < nch; ch++) {
        int y0 = ch * 32;
        float s[32];
        #pragma unroll
        for (int i = 0; i < 32; i++) s[i] = 0.f;
        #pragma unroll
        for (int c = 0; c < 16; c++) {
            const float4* kp = (const float4*)(kt + c * TT + y0);
            float qc = q[c];
            #pragma unroll
            for (int j = 0; j < 8; j++) {
                float4 k4 = kp[j];
                s[4*j+0] = fmaf(qc, k4.x, s[4*j+0]);
                s[4*j+1] = fmaf(qc, k4.y, s[4*j+1]);
                s[4*j+2] = fmaf(qc, k4.z, s[4*j+2]);
                s[4*j+3] = fmaf(qc, k4.w, s[4*j+3]);
            }
        }
        if (y0 + 31 > t) {                 // causal mask only touches last chunk
            #pragma unroll
            for (int i = 0; i < 32; i++) if (y0 + i > t) s[i] = -3e38f;
        }
        float cm = s[0];
        #pragma unroll
        for (int i = 1; i < 32; i++) cm = fmaxf(cm, s[i]);
        float nm = fmaxf(mx, cm);
        float corr = __expf(mx - nm);
        l *= corr;
        #pragma unroll
        for (int c = 0; c < 16; c++) acc[c] *= corr;
        float ps = 0.f;
        #pragma unroll
        for (int i = 0; i < 32; i++) { s[i] = __expf(s[i] - nm); ps += s[i]; }
        l += ps;
        #pragma unroll
        for (int c = 0; c < 16; c++) {
            const float4* vp = (const float4*)(vf + c * TT + y0);
            float a = acc[c];
            #pragma unroll
            for (int j = 0; j < 8; j++) {
                float4 v4 = vp[j];
                a = fmaf(s[4*j+0], v4.x, a);
                a = fmaf(s[4*j+1], v4.y, a);
                a = fmaf(s[4*j+2], v4.z, a);
                a = fmaf(s[4*j+3], v4.w, a);
            }
            acc[c] = a;
        }
        mx = nm;
    }
    float inv = 1.f / l;
    #pragma unroll
    for (int c = 0; c < 16; c++) acc[c] *= inv;

    size_t obase = (((size_t)b * CC) * FF + f) * TT + t;
    #pragma unroll 8
    for (int oc = 0; oc < CC; oc++) {
        const float4* wr = (const float4*)(wp + oc * 16);
        float4 w0 = wr[0], w1 = wr[1], w2 = wr[2], w3 = wr[3];
        float r = 0.f;
        r = fmaf(w0.x, acc[0],  r); r = fmaf(w0.y, acc[1],  r);
        r = fmaf(w0.z, acc[2],  r); r = fmaf(w0.w, acc[3],  r);
        r = fmaf(w1.x, acc[4],  r); r = fmaf(w1.y, acc[5],  r);
        r = fmaf(w1.z, acc[6],  r); r = fmaf(w1.w, acc[7],  r);
        r = fmaf(w2.x, acc[8],  r); r = fmaf(w2.y, acc[9],  r);
        r = fmaf(w2.z, acc[10], r); r = fmaf(w2.w, acc[11], r);
        r = fmaf(w3.x, acc[12], r); r = fmaf(w3.y, acc[13], r);
        r = fmaf(w3.z, acc[14], r); r = fmaf(w3.w, acc[15], r);
        r = fmaf(r, sc3[oc], sh3[oc]);
        r = r > 0.f ? r : al3[oc] * r;
        out[obase + (size_t)oc * SP] = r + inp[obase + (size_t)oc * SP];
    }
}

// ---------------- launcher ----------------
extern "C" void kernel_launch(void* const* d_in, const int* in_sizes, int n_in,
                              void* d_out, int out_size)
{
    (void)in_sizes; (void)n_in; (void)out_size;
    const float* inp    = (const float*)d_in[0];
    // d_in[1] = mask (causal triu, rebuilt analytically; unused)
    const float* w_fqkv = (const float*)d_in[2];
    const float* g1 = (const float*)d_in[3];
    const float* b1 = (const float*)d_in[4];
    const float* m1 = (const float*)d_in[5];
    const float* v1 = (const float*)d_in[6];
    const float* a1 = (const float*)d_in[7];
    const float* w_tqk  = (const float*)d_in[8];
    const float* g2 = (const float*)d_in[9];
    const float* b2 = (const float*)d_in[10];
    const float* m2 = (const float*)d_in[11];
    const float* v2 = (const float*)d_in[12];
    const float* a2 = (const float*)d_in[13];
    const float* w_proj = (const float*)d_in[14];
    const float* g3 = (const float*)d_in[15];
    const float* b3 = (const float*)d_in[16];
    const float* m3 = (const float*)d_in[17];
    const float* v3 = (const float*)d_in[18];
    const float* a3 = (const float*)d_in[19];
    float* out = (float*)d_out;

    cudaFuncSetAttribute(asa_time_attn_kernel,
                         cudaFuncAttributeMaxDynamicSharedMemorySize, 14016 * 4);

    asa_conv_qkv_kernel<<<dim3(FF, BB), 128>>>(inp, w_fqkv, w_tqk,
        g1, b1, m1, v1, a1, g2, b2, m2, v2, a2);
    asa_transpose_qkv_kernel<<<dim3(13, 8, BB * 48), dim3(32, 8)>>>();
    asa_freq_attn_kernel<<<dim3(TT, BB), 256>>>();
    asa_transpose_fout_kernel<<<dim3(8, 13, BB * 16), dim3(32, 8)>>>();
    asa_time_attn_kernel<<<dim3(FF, BB), 416, 14016 * 4>>>(inp, w_proj,
        g3, b3, m3, v3, a3, out);
}